// round 6
// baseline (speedup 1.0000x reference)
#include <cuda_runtime.h>
#include <cuda_fp16.h>
#include <cstdint>

#define TOK   4096
#define HID   2048
#define INTER 5632

// ---- scratch (device globals; no runtime allocation allowed) ----
__device__ __half g_xh[(size_t)TOK * HID];      // x in fp16
__device__ __half g_wg[(size_t)INTER * HID];    // gate_w fp16
__device__ __half g_wu[(size_t)INTER * HID];    // up_w fp16
__device__ __half g_wd[(size_t)HID * INTER];    // down_w fp16
__device__ __half g_hbuf[(size_t)TOK * INTER];  // hidden activation fp16

// ---- fp32 -> fp16 conversion, vectorized ----
__global__ void convert_f2h(const float* __restrict__ in, __half* __restrict__ out, int n4) {
  int i = blockIdx.x * blockDim.x + threadIdx.x;
  int stride = gridDim.x * blockDim.x;
  for (; i < n4; i += stride) {
    float4 v = reinterpret_cast<const float4*>(in)[i];
    __half2 h0 = __floats2half2_rn(v.x, v.y);
    __half2 h1 = __floats2half2_rn(v.z, v.w);
    reinterpret_cast<__half2*>(out)[2 * i]     = h0;
    reinterpret_cast<__half2*>(out)[2 * i + 1] = h1;
  }
}

// =====================================================================
// helpers
// =====================================================================
__device__ __forceinline__ uint32_t smem_u32(const void* p) {
  uint32_t a;
  asm("{ .reg .u64 t; cvta.to.shared.u64 t, %1; cvt.u32.u64 %0, t; }" : "=r"(a) : "l"(p));
  return a;
}

__device__ __forceinline__ void mma16816(float* c, const uint32_t* a, const uint32_t* b) {
  asm volatile(
      "mma.sync.aligned.m16n8k16.row.col.f32.f16.f16.f32 "
      "{%0,%1,%2,%3}, {%4,%5,%6,%7}, {%8,%9}, {%0,%1,%2,%3};\n"
      : "+f"(c[0]), "+f"(c[1]), "+f"(c[2]), "+f"(c[3])
      : "r"(a[0]), "r"(a[1]), "r"(a[2]), "r"(a[3]), "r"(b[0]), "r"(b[1]));
}

__device__ __forceinline__ void ldsm4(uint32_t* r, uint32_t addr) {
  asm volatile("ldmatrix.sync.aligned.m8n8.x4.shared.b16 {%0,%1,%2,%3}, [%4];"
               : "=r"(r[0]), "=r"(r[1]), "=r"(r[2]), "=r"(r[3]) : "r"(addr));
}

__device__ __forceinline__ void cp16(uint32_t s, const void* g) {
  asm volatile("cp.async.cg.shared.global [%0], [%1], 16;" :: "r"(s), "l"(g));
}
#define CP_COMMIT() asm volatile("cp.async.commit_group;" ::: "memory")

// stage: A (256 rows x 128B = 32KB) then B (128 rows x 128B = 16KB) = 48KB
#define STAGE_B 49152u
#define A_B     32768u
#define NSTAGE  3

// BK = 64 halves = 128 B/row; swizzle: row*128 + ((c ^ (row&7)) << 4)

// =====================================================================
// GEMM1 fused gate+up. CTA: M=256 tokens x 64 real I-cols. BK=64.
// B smem = [Wg rows 0..63 ; Wu rows 64..127].
// 8 warps: wm=warp>>1 (64 rows), wn=warp&1 (0=gate matrix, 1=up matrix).
// Warp tile 64x64. Epilogue: gate warps stage scaled g via smem; up warps
// compute h = silu(g)*u and store fp16.
// =====================================================================
__global__ __launch_bounds__(256, 1)
void gemm1_mma(const __half* __restrict__ X, const __half* __restrict__ Wg,
               const __half* __restrict__ Wu, const float* __restrict__ gs,
               const float* __restrict__ us, __half* __restrict__ Hout) {
  extern __shared__ char smem[];
  const uint32_t sb = smem_u32(smem);
  const int tid = threadIdx.x, lane = tid & 31, warp = tid >> 5;
  const int wm = warp >> 1, wn = warp & 1;
  const int mBase = blockIdx.y * 256;
  const int nBase = blockIdx.x * 64;
  const int s7 = lane & 7;

  const uint32_t aRow = (uint32_t)((wm * 64 + (lane & 15)) * 128);
  const int hiA = lane >> 4;
  const uint32_t bRow = (uint32_t)((wn * 64 + (lane & 7) + ((lane >> 4) & 1) * 8) * 128);
  const int cB = (lane >> 3) & 1;

  float acc[4][8][4];
#pragma unroll
  for (int i = 0; i < 4; i++)
#pragma unroll
    for (int j = 0; j < 8; j++)
#pragma unroll
      for (int k = 0; k < 4; k++) acc[i][j][k] = 0.f;

  auto load_stage = [&](int kt, int b) {
    const uint32_t base = sb + (uint32_t)b * STAGE_B;
    const int k0 = kt * 64;
#pragma unroll
    for (int i = 0; i < 8; i++) {               // A: 2048 16B-chunks
      int ch = tid + i * 256;
      int row = ch >> 3, c = ch & 7;
      uint32_t sw = (uint32_t)(row * 128 + ((c ^ (row & 7)) << 4));
      cp16(base + sw, X + (size_t)(mBase + row) * HID + k0 + c * 8);
    }
#pragma unroll
    for (int i = 0; i < 2; i++) {               // Wg rows 0..63 (512 chunks)
      int ch = tid + i * 256;
      int row = ch >> 3, c = ch & 7;
      uint32_t sw = (uint32_t)(row * 128 + ((c ^ (row & 7)) << 4));
      cp16(base + A_B + sw, Wg + (size_t)(nBase + row) * HID + k0 + c * 8);
    }
#pragma unroll
    for (int i = 0; i < 2; i++) {               // Wu rows 64..127
      int ch = tid + i * 256;
      int row = ch >> 3, c = ch & 7;
      uint32_t sw = (uint32_t)((row + 64) * 128 + ((c ^ (row & 7)) << 4));
      cp16(base + A_B + sw, Wu + (size_t)(nBase + row) * HID + k0 + c * 8);
    }
    CP_COMMIT();
  };

  const int KT = HID / 64;  // 32
  load_stage(0, 0);
  load_stage(1, 1);

  for (int kt = 0; kt < KT; kt++) {
    if (kt + 1 < KT) asm volatile("cp.async.wait_group 1;" ::: "memory");
    else             asm volatile("cp.async.wait_group 0;" ::: "memory");
    __syncthreads();

    if (kt + 2 < KT) load_stage(kt + 2, (kt + 2) % NSTAGE);

    const uint32_t base = sb + (uint32_t)(kt % NSTAGE) * STAGE_B;
    const uint32_t aB = base + aRow;
    const uint32_t bB = base + A_B + bRow;
#pragma unroll
    for (int kk = 0; kk < 4; kk++) {
      const uint32_t aOff = (uint32_t)((((kk * 2 + hiA) ^ s7)) << 4);
      uint32_t a[4][4];
#pragma unroll
      for (int mt = 0; mt < 4; mt++) ldsm4(a[mt], aB + (uint32_t)(mt * 2048) + aOff);
      const uint32_t bOff = (uint32_t)((((kk * 2 + cB) ^ s7)) << 4);
      uint32_t bf[4][4];
#pragma unroll
      for (int np = 0; np < 4; np++) ldsm4(bf[np], bB + (uint32_t)(np * 2048) + bOff);
#pragma unroll
      for (int mt = 0; mt < 4; mt++)
#pragma unroll
        for (int np = 0; np < 4; np++) {
          mma16816(acc[mt][np * 2 + 0], a[mt], &bf[np][0]);
          mma16816(acc[mt][np * 2 + 1], a[mt], &bf[np][2]);
        }
    }
  }
  __syncthreads();   // smem now free for gate exchange buffer

  // epilogue
  const int g = lane >> 2, t = lane & 3;
  float* gbuf = reinterpret_cast<float*>(smem);   // [256][68] floats (padded)

  if (wn == 0) {     // gate warps: scale and stage to smem
#pragma unroll
    for (int mt = 0; mt < 4; mt++) {
#pragma unroll
      for (int n8 = 0; n8 < 8; n8++) {
        const int co = (n8 >> 1) * 16 + (n8 & 1) * 8 + 2 * t;
        const float gs0 = __ldg(gs + nBase + co), gs1 = __ldg(gs + nBase + co + 1);
        const int rl = wm * 64 + mt * 16 + g;
        const float* cc = acc[mt][n8];
        *reinterpret_cast<float2*>(gbuf + (size_t)rl * 68 + co) =
            make_float2(cc[0] * gs0, cc[1] * gs1);
        *reinterpret_cast<float2*>(gbuf + (size_t)(rl + 8) * 68 + co) =
            make_float2(cc[2] * gs0, cc[3] * gs1);
      }
    }
  }
  __syncthreads();
  if (wn == 1) {     // up warps: combine & store
#pragma unroll
    for (int mt = 0; mt < 4; mt++) {
#pragma unroll
      for (int n8 = 0; n8 < 8; n8++) {
        const int co = (n8 >> 1) * 16 + (n8 & 1) * 8 + 2 * t;
        const float us0 = __ldg(us + nBase + co), us1 = __ldg(us + nBase + co + 1);
        const int rl = wm * 64 + mt * 16 + g;
        const float* cc = acc[mt][n8];

        float2 gv0 = *reinterpret_cast<const float2*>(gbuf + (size_t)rl * 68 + co);
        float2 gv1 = *reinterpret_cast<const float2*>(gbuf + (size_t)(rl + 8) * 68 + co);
        float u00 = cc[0] * us0, u01 = cc[1] * us1;
        float u10 = cc[2] * us0, u11 = cc[3] * us1;

        float h00 = gv0.x / (1.f + expf(-gv0.x)) * u00;
        float h01 = gv0.y / (1.f + expf(-gv0.y)) * u01;
        float h10 = gv1.x / (1.f + expf(-gv1.x)) * u10;
        float h11 = gv1.y / (1.f + expf(-gv1.y)) * u11;

        *reinterpret_cast<__half2*>(Hout + (size_t)(mBase + rl) * INTER + nBase + co) =
            __floats2half2_rn(h00, h01);
        *reinterpret_cast<__half2*>(Hout + (size_t)(mBase + rl + 8) * INTER + nBase + co) =
            __floats2half2_rn(h10, h11);
      }
    }
  }
}

// =====================================================================
// GEMM2: out = (H @ Wd^T) * ds, fp32 out. CTA: M=256 x N=128, BK=64.
// 8 warps: wm=warp>>1 (64 rows), wn=warp&1 (64 cols). Warp tile 64x64.
// =====================================================================
__global__ __launch_bounds__(256, 1)
void gemm2_mma(const __half* __restrict__ H, const __half* __restrict__ Wd,
               const float* __restrict__ ds, float* __restrict__ Out) {
  extern __shared__ char smem[];
  const uint32_t sb = smem_u32(smem);
  const int tid = threadIdx.x, lane = tid & 31, warp = tid >> 5;
  const int wm = warp >> 1, wn = warp & 1;
  const int mBase = blockIdx.y * 256;
  const int nBase = blockIdx.x * 128;
  const int s7 = lane & 7;

  const uint32_t aRow = (uint32_t)((wm * 64 + (lane & 15)) * 128);
  const int hiA = lane >> 4;
  const uint32_t bRow = (uint32_t)((wn * 64 + (lane & 7) + ((lane >> 4) & 1) * 8) * 128);
  const int cB = (lane >> 3) & 1;

  float acc[4][8][4];
#pragma unroll
  for (int i = 0; i < 4; i++)
#pragma unroll
    for (int j = 0; j < 8; j++)
#pragma unroll
      for (int k = 0; k < 4; k++) acc[i][j][k] = 0.f;

  auto load_stage = [&](int kt, int b) {
    const uint32_t base = sb + (uint32_t)b * STAGE_B;
    const int k0 = kt * 64;
#pragma unroll
    for (int i = 0; i < 8; i++) {               // A: 2048 chunks
      int ch = tid + i * 256;
      int row = ch >> 3, c = ch & 7;
      uint32_t sw = (uint32_t)(row * 128 + ((c ^ (row & 7)) << 4));
      cp16(base + sw, H + (size_t)(mBase + row) * INTER + k0 + c * 8);
    }
#pragma unroll
    for (int i = 0; i < 4; i++) {               // B: 128 rows (1024 chunks)
      int ch = tid + i * 256;
      int row = ch >> 3, c = ch & 7;
      uint32_t sw = (uint32_t)(row * 128 + ((c ^ (row & 7)) << 4));
      cp16(base + A_B + sw, Wd + (size_t)(nBase + row) * INTER + k0 + c * 8);
    }
    CP_COMMIT();
  };

  const int KT = INTER / 64;  // 88
  load_stage(0, 0);
  load_stage(1, 1);

  for (int kt = 0; kt < KT; kt++) {
    if (kt + 1 < KT) asm volatile("cp.async.wait_group 1;" ::: "memory");
    else             asm volatile("cp.async.wait_group 0;" ::: "memory");
    __syncthreads();

    if (kt + 2 < KT) load_stage(kt + 2, (kt + 2) % NSTAGE);

    const uint32_t base = sb + (uint32_t)(kt % NSTAGE) * STAGE_B;
    const uint32_t aB = base + aRow;
    const uint32_t bB = base + A_B + bRow;
#pragma unroll
    for (int kk = 0; kk < 4; kk++) {
      const uint32_t aOff = (uint32_t)((((kk * 2 + hiA) ^ s7)) << 4);
      uint32_t a[4][4];
#pragma unroll
      for (int mt = 0; mt < 4; mt++) ldsm4(a[mt], aB + (uint32_t)(mt * 2048) + aOff);
      const uint32_t bOff = (uint32_t)((((kk * 2 + cB) ^ s7)) << 4);
      uint32_t bf[4][4];
#pragma unroll
      for (int np = 0; np < 4; np++) ldsm4(bf[np], bB + (uint32_t)(np * 2048) + bOff);
#pragma unroll
      for (int mt = 0; mt < 4; mt++)
#pragma unroll
        for (int np = 0; np < 4; np++) {
          mma16816(acc[mt][np * 2 + 0], a[mt], &bf[np][0]);
          mma16816(acc[mt][np * 2 + 1], a[mt], &bf[np][2]);
        }
    }
  }

  const int g = lane >> 2, t = lane & 3;
#pragma unroll
  for (int mt = 0; mt < 4; mt++) {
#pragma unroll
    for (int n8 = 0; n8 < 8; n8++) {
      const int col = nBase + wn * 64 + (n8 >> 1) * 16 + (n8 & 1) * 8 + 2 * t;
      const float d0 = __ldg(ds + col), d1 = __ldg(ds + col + 1);
      const float* cc = acc[mt][n8];
      const int r = mBase + wm * 64 + mt * 16 + g;
      *reinterpret_cast<float2*>(Out + (size_t)r * HID + col) =
          make_float2(cc[0] * d0, cc[1] * d1);
      *reinterpret_cast<float2*>(Out + (size_t)(r + 8) * HID + col) =
          make_float2(cc[2] * d0, cc[3] * d1);
    }
  }
}

// =====================================================================
extern "C" void kernel_launch(void* const* d_in, const int* in_sizes, int n_in,
                              void* d_out, int out_size) {
  const float* x      = (const float*)d_in[0];
  const float* gate_w = (const float*)d_in[1];
  const float* up_w   = (const float*)d_in[2];
  const float* down_w = (const float*)d_in[3];
  const float* gate_s = (const float*)d_in[4];
  const float* up_s   = (const float*)d_in[5];
  const float* down_s = (const float*)d_in[6];
  float* out = (float*)d_out;

  __half *xh, *wg, *wu, *wd, *hb;
  cudaGetSymbolAddress((void**)&xh, g_xh);
  cudaGetSymbolAddress((void**)&wg, g_wg);
  cudaGetSymbolAddress((void**)&wu, g_wu);
  cudaGetSymbolAddress((void**)&wd, g_wd);
  cudaGetSymbolAddress((void**)&hb, g_hbuf);

  const int SMEM = NSTAGE * (int)STAGE_B;  // 147456 B, 1 CTA/SM
  cudaFuncSetAttribute(gemm1_mma, cudaFuncAttributeMaxDynamicSharedMemorySize, SMEM);
  cudaFuncSetAttribute(gemm2_mma, cudaFuncAttributeMaxDynamicSharedMemorySize, SMEM);

  const int n4x = (TOK * HID) / 4;
  const int n4w = (INTER * HID) / 4;
  convert_f2h<<<2048, 256>>>(x, xh, n4x);
  convert_f2h<<<2048, 256>>>(gate_w, wg, n4w);
  convert_f2h<<<2048, 256>>>(up_w, wu, n4w);
  convert_f2h<<<2048, 256>>>(down_w, wd, n4w);

  dim3 grid1(INTER / 64, TOK / 256);   // (88, 16)
  gemm1_mma<<<grid1, 256, SMEM>>>(xh, wg, wu, gate_s, up_s, hb);

  dim3 grid2(HID / 128, TOK / 256);    // (16, 16)
  gemm2_mma<<<grid2, 256, SMEM>>>(hb, wd, down_s, out);
}

// round 9
// speedup vs baseline: 1.0403x; 1.0403x over previous
#include <cuda_runtime.h>
#include <cuda_fp16.h>
#include <cstdint>

#define TOK   4096
#define HID   2048
#define INTER 5632

// ---- scratch (device globals; no runtime allocation allowed) ----
__device__ __half g_xh[(size_t)TOK * HID];
__device__ __half g_wg[(size_t)INTER * HID];
__device__ __half g_wu[(size_t)INTER * HID];
__device__ __half g_wd[(size_t)HID * INTER];
__device__ __half g_hbuf[(size_t)TOK * INTER];

__global__ void convert_f2h(const float* __restrict__ in, __half* __restrict__ out, int n4) {
  int i = blockIdx.x * blockDim.x + threadIdx.x;
  int stride = gridDim.x * blockDim.x;
  for (; i < n4; i += stride) {
    float4 v = reinterpret_cast<const float4*>(in)[i];
    __half2 h0 = __floats2half2_rn(v.x, v.y);
    __half2 h1 = __floats2half2_rn(v.z, v.w);
    reinterpret_cast<__half2*>(out)[2 * i]     = h0;
    reinterpret_cast<__half2*>(out)[2 * i + 1] = h1;
  }
}

// =====================================================================
// helpers
// =====================================================================
__device__ __forceinline__ uint32_t smem_u32(const void* p) {
  uint32_t a;
  asm("{ .reg .u64 t; cvta.to.shared.u64 t, %1; cvt.u32.u64 %0, t; }" : "=r"(a) : "l"(p));
  return a;
}

__device__ __forceinline__ void mma16816(float* c, const uint32_t* a, const uint32_t* b) {
  asm volatile(
      "mma.sync.aligned.m16n8k16.row.col.f32.f16.f16.f32 "
      "{%0,%1,%2,%3}, {%4,%5,%6,%7}, {%8,%9}, {%0,%1,%2,%3};\n"
      : "+f"(c[0]), "+f"(c[1]), "+f"(c[2]), "+f"(c[3])
      : "r"(a[0]), "r"(a[1]), "r"(a[2]), "r"(a[3]), "r"(b[0]), "r"(b[1]));
}

__device__ __forceinline__ void ldsm4(uint32_t* r, uint32_t addr) {
  asm volatile("ldmatrix.sync.aligned.m8n8.x4.shared.b16 {%0,%1,%2,%3}, [%4];"
               : "=r"(r[0]), "=r"(r[1]), "=r"(r[2]), "=r"(r[3]) : "r"(addr));
}

__device__ __forceinline__ void cp16(uint32_t s, const void* g) {
  asm volatile("cp.async.cg.shared.global [%0], [%1], 16;" :: "r"(s), "l"(g));
}
#define CP_COMMIT() asm volatile("cp.async.commit_group;" ::: "memory")

// stage: A (256 rows x 128B = 32KB) + B (128 rows x 128B = 16KB) = 48KB
#define STAGE_B 49152u
#define A_B     32768u
#define NSTAGE  3
// BK = 64 halves = 128 B/row; swizzled offset: row*128 + ((c ^ (row&7)) << 4)

// =====================================================================
// GEMM1 fused gate+up. CTA: 256 tokens x 64 I-cols, 512 thr (16 warps).
// Warps: wm=warp>>2 (4 x 64 rows), wn=warp&3: mat=wn>>1 (0=gate,1=up),
// cg=wn&1 (32-col group). Warp tile 64x32.
// B smem rows: gate 0..63, up 64..127.
// Epilogue: gate warps stage scaled g via smem; up warps silu*u -> fp16.
// =====================================================================
__global__ __launch_bounds__(512, 1)
void gemm1_mma(const __half* __restrict__ X, const __half* __restrict__ Wg,
               const __half* __restrict__ Wu, const float* __restrict__ gs,
               const float* __restrict__ us, __half* __restrict__ Hout) {
  extern __shared__ char smem[];
  const uint32_t sb = smem_u32(smem);
  const int tid = threadIdx.x, lane = tid & 31, warp = tid >> 5;
  const int wm = warp >> 2, wn = warp & 3;
  const int mat = wn >> 1, cg = wn & 1;
  const int mBase = blockIdx.y * 256;
  const int nBase = blockIdx.x * 64;
  const int s7 = lane & 7;

  const uint32_t aRow = (uint32_t)((wm * 64 + (lane & 15)) * 128);
  const int hiA = lane >> 4;
  const int bRowIdx = mat * 64 + cg * 32;
  const uint32_t bRow = (uint32_t)((bRowIdx + (lane & 7) + ((lane >> 4) & 1) * 8) * 128);
  const int cB = (lane >> 3) & 1;

  float acc[4][4][4];
#pragma unroll
  for (int i = 0; i < 4; i++)
#pragma unroll
    for (int j = 0; j < 4; j++)
#pragma unroll
      for (int k = 0; k < 4; k++) acc[i][j][k] = 0.f;

  auto load_stage = [&](int kt, int b) {
    const uint32_t base = sb + (uint32_t)b * STAGE_B;
    const int k0 = kt * 64;
#pragma unroll
    for (int i = 0; i < 4; i++) {               // A: 2048 chunks / 512 thr
      int ch = tid + i * 512;
      int row = ch >> 3, c = ch & 7;
      uint32_t sw = (uint32_t)(row * 128 + ((c ^ (row & 7)) << 4));
      cp16(base + sw, X + (size_t)(mBase + row) * HID + k0 + c * 8);
    }
    {                                           // Wg rows 0..63 + Wu rows 64..127
      int row = tid >> 3, c = tid & 7;
      uint32_t swg = (uint32_t)(row * 128 + ((c ^ (row & 7)) << 4));
      cp16(base + A_B + swg, Wg + (size_t)(nBase + row) * HID + k0 + c * 8);
      uint32_t swu = (uint32_t)((row + 64) * 128 + ((c ^ (row & 7)) << 4));
      cp16(base + A_B + swu, Wu + (size_t)(nBase + row) * HID + k0 + c * 8);
    }
    CP_COMMIT();
  };

  const int KT = HID / 64;  // 32
  load_stage(0, 0);
  load_stage(1, 1);

  for (int kt = 0; kt < KT; kt++) {
    if (kt + 1 < KT) asm volatile("cp.async.wait_group 1;" ::: "memory");
    else             asm volatile("cp.async.wait_group 0;" ::: "memory");
    __syncthreads();

    if (kt + 2 < KT) load_stage(kt + 2, (kt + 2) % NSTAGE);

    const uint32_t base = sb + (uint32_t)(kt % NSTAGE) * STAGE_B;
    const uint32_t aB = base + aRow;
    const uint32_t bB = base + A_B + bRow;
#pragma unroll
    for (int kk = 0; kk < 4; kk++) {
      const uint32_t aOff = (uint32_t)((((kk * 2 + hiA) ^ s7)) << 4);
      uint32_t a[4][4];
#pragma unroll
      for (int mt = 0; mt < 4; mt++) ldsm4(a[mt], aB + (uint32_t)(mt * 2048) + aOff);
      const uint32_t bOff = (uint32_t)((((kk * 2 + cB) ^ s7)) << 4);
      uint32_t bf[2][4];
#pragma unroll
      for (int np = 0; np < 2; np++) ldsm4(bf[np], bB + (uint32_t)(np * 2048) + bOff);
#pragma unroll
      for (int mt = 0; mt < 4; mt++)
#pragma unroll
        for (int np = 0; np < 2; np++) {
          mma16816(acc[mt][np * 2 + 0], a[mt], &bf[np][0]);
          mma16816(acc[mt][np * 2 + 1], a[mt], &bf[np][2]);
        }
    }
  }
  __syncthreads();   // stage smem free -> reuse as gate exchange buffer

  const int g = lane >> 2, t = lane & 3;
  float* gbuf = reinterpret_cast<float*>(smem);   // [256][66]

  if (mat == 0) {    // gate warps: scale, stage to smem
#pragma unroll
    for (int mt = 0; mt < 4; mt++) {
#pragma unroll
      for (int n8 = 0; n8 < 4; n8++) {
        const int co = cg * 32 + (n8 >> 1) * 16 + (n8 & 1) * 8 + 2 * t;
        const float gs0 = __ldg(gs + nBase + co), gs1 = __ldg(gs + nBase + co + 1);
        const int rl = wm * 64 + mt * 16 + g;
        const float* cc = acc[mt][n8];
        *reinterpret_cast<float2*>(gbuf + (size_t)rl * 66 + co) =
            make_float2(cc[0] * gs0, cc[1] * gs1);
        *reinterpret_cast<float2*>(gbuf + (size_t)(rl + 8) * 66 + co) =
            make_float2(cc[2] * gs0, cc[3] * gs1);
      }
    }
  }
  __syncthreads();
  if (mat == 1) {    // up warps: combine & store fp16
#pragma unroll
    for (int mt = 0; mt < 4; mt++) {
#pragma unroll
      for (int n8 = 0; n8 < 4; n8++) {
        const int co = cg * 32 + (n8 >> 1) * 16 + (n8 & 1) * 8 + 2 * t;
        const float us0 = __ldg(us + nBase + co), us1 = __ldg(us + nBase + co + 1);
        const int rl = wm * 64 + mt * 16 + g;
        const float* cc = acc[mt][n8];

        float2 gv0 = *reinterpret_cast<const float2*>(gbuf + (size_t)rl * 66 + co);
        float2 gv1 = *reinterpret_cast<const float2*>(gbuf + (size_t)(rl + 8) * 66 + co);
        float u00 = cc[0] * us0, u01 = cc[1] * us1;
        float u10 = cc[2] * us0, u11 = cc[3] * us1;

        float h00 = gv0.x / (1.f + expf(-gv0.x)) * u00;
        float h01 = gv0.y / (1.f + expf(-gv0.y)) * u01;
        float h10 = gv1.x / (1.f + expf(-gv1.x)) * u10;
        float h11 = gv1.y / (1.f + expf(-gv1.y)) * u11;

        *reinterpret_cast<__half2*>(Hout + (size_t)(mBase + rl) * INTER + nBase + co) =
            __floats2half2_rn(h00, h01);
        *reinterpret_cast<__half2*>(Hout + (size_t)(mBase + rl + 8) * INTER + nBase + co) =
            __floats2half2_rn(h10, h11);
      }
    }
  }
}

// =====================================================================
// GEMM2: out = (H @ Wd^T) * ds, fp32. CTA 256x128, 512 thr, 16 warps
// 4(m)x4(n), warp tile 64x32. BK=64, 3-stage.
// =====================================================================
__global__ __launch_bounds__(512, 1)
void gemm2_mma(const __half* __restrict__ H, const __half* __restrict__ Wd,
               const float* __restrict__ ds, float* __restrict__ Out) {
  extern __shared__ char smem[];
  const uint32_t sb = smem_u32(smem);
  const int tid = threadIdx.x, lane = tid & 31, warp = tid >> 5;
  const int wm = warp >> 2, wn = warp & 3;
  const int mBase = blockIdx.y * 256;
  const int nBase = blockIdx.x * 128;
  const int s7 = lane & 7;

  const uint32_t aRow = (uint32_t)((wm * 64 + (lane & 15)) * 128);
  const int hiA = lane >> 4;
  const uint32_t bRow = (uint32_t)((wn * 32 + (lane & 7) + ((lane >> 4) & 1) * 8) * 128);
  const int cB = (lane >> 3) & 1;

  float acc[4][4][4];
#pragma unroll
  for (int i = 0; i < 4; i++)
#pragma unroll
    for (int j = 0; j < 4; j++)
#pragma unroll
      for (int k = 0; k < 4; k++) acc[i][j][k] = 0.f;

  auto load_stage = [&](int kt, int b) {
    const uint32_t base = sb + (uint32_t)b * STAGE_B;
    const int k0 = kt * 64;
#pragma unroll
    for (int i = 0; i < 4; i++) {               // A: 2048 chunks
      int ch = tid + i * 512;
      int row = ch >> 3, c = ch & 7;
      uint32_t sw = (uint32_t)(row * 128 + ((c ^ (row & 7)) << 4));
      cp16(base + sw, H + (size_t)(mBase + row) * INTER + k0 + c * 8);
    }
#pragma unroll
    for (int i = 0; i < 2; i++) {               // B: 128 rows = 1024 chunks
      int ch = tid + i * 512;
      int row = ch >> 3, c = ch & 7;
      uint32_t sw = (uint32_t)(row * 128 + ((c ^ (row & 7)) << 4));
      cp16(base + A_B + sw, Wd + (size_t)(nBase + row) * INTER + k0 + c * 8);
    }
    CP_COMMIT();
  };

  const int KT = INTER / 64;  // 88
  load_stage(0, 0);
  load_stage(1, 1);

  for (int kt = 0; kt < KT; kt++) {
    if (kt + 1 < KT) asm volatile("cp.async.wait_group 1;" ::: "memory");
    else             asm volatile("cp.async.wait_group 0;" ::: "memory");
    __syncthreads();

    if (kt + 2 < KT) load_stage(kt + 2, (kt + 2) % NSTAGE);

    const uint32_t base = sb + (uint32_t)(kt % NSTAGE) * STAGE_B;
    const uint32_t aB = base + aRow;
    const uint32_t bB = base + A_B + bRow;
#pragma unroll
    for (int kk = 0; kk < 4; kk++) {
      const uint32_t aOff = (uint32_t)((((kk * 2 + hiA) ^ s7)) << 4);
      uint32_t a[4][4];
#pragma unroll
      for (int mt = 0; mt < 4; mt++) ldsm4(a[mt], aB + (uint32_t)(mt * 2048) + aOff);
      const uint32_t bOff = (uint32_t)((((kk * 2 + cB) ^ s7)) << 4);
      uint32_t bf[2][4];
#pragma unroll
      for (int np = 0; np < 2; np++) ldsm4(bf[np], bB + (uint32_t)(np * 2048) + bOff);
#pragma unroll
      for (int mt = 0; mt < 4; mt++)
#pragma unroll
        for (int np = 0; np < 2; np++) {
          mma16816(acc[mt][np * 2 + 0], a[mt], &bf[np][0]);
          mma16816(acc[mt][np * 2 + 1], a[mt], &bf[np][2]);
        }
    }
  }

  const int g = lane >> 2, t = lane & 3;
#pragma unroll
  for (int mt = 0; mt < 4; mt++) {
#pragma unroll
    for (int n8 = 0; n8 < 4; n8++) {
      const int col = nBase + wn * 32 + (n8 >> 1) * 16 + (n8 & 1) * 8 + 2 * t;
      const float d0 = __ldg(ds + col), d1 = __ldg(ds + col + 1);
      const float* cc = acc[mt][n8];
      const int r = mBase + wm * 64 + mt * 16 + g;
      *reinterpret_cast<float2*>(Out + (size_t)r * HID + col) =
          make_float2(cc[0] * d0, cc[1] * d1);
      *reinterpret_cast<float2*>(Out + (size_t)(r + 8) * HID + col) =
          make_float2(cc[2] * d0, cc[3] * d1);
    }
  }
}

// =====================================================================
extern "C" void kernel_launch(void* const* d_in, const int* in_sizes, int n_in,
                              void* d_out, int out_size) {
  const float* x      = (const float*)d_in[0];
  const float* gate_w = (const float*)d_in[1];
  const float* up_w   = (const float*)d_in[2];
  const float* down_w = (const float*)d_in[3];
  const float* gate_s = (const float*)d_in[4];
  const float* up_s   = (const float*)d_in[5];
  const float* down_s = (const float*)d_in[6];
  float* out = (float*)d_out;

  __half *xh, *wg, *wu, *wd, *hb;
  cudaGetSymbolAddress((void**)&xh, g_xh);
  cudaGetSymbolAddress((void**)&wg, g_wg);
  cudaGetSymbolAddress((void**)&wu, g_wu);
  cudaGetSymbolAddress((void**)&wd, g_wd);
  cudaGetSymbolAddress((void**)&hb, g_hbuf);

  const int SMEM = NSTAGE * (int)STAGE_B;  // 147456 B
  cudaFuncSetAttribute(gemm1_mma, cudaFuncAttributeMaxDynamicSharedMemorySize, SMEM);
  cudaFuncSetAttribute(gemm2_mma, cudaFuncAttributeMaxDynamicSharedMemorySize, SMEM);

  const int n4x = (TOK * HID) / 4;
  const int n4w = (INTER * HID) / 4;
  convert_f2h<<<2048, 256>>>(x, xh, n4x);
  convert_f2h<<<2048, 256>>>(gate_w, wg, n4w);
  convert_f2h<<<2048, 256>>>(up_w, wu, n4w);
  convert_f2h<<<2048, 256>>>(down_w, wd, n4w);

  dim3 grid1(INTER / 64, TOK / 256);   // (88, 16)
  gemm1_mma<<<grid1, 512, SMEM>>>(xh, wg, wu, gate_s, up_s, hb);

  dim3 grid2(HID / 128, TOK / 256);    // (16, 16)
  gemm2_mma<<<grid2, 512, SMEM>>>(hb, wd, down_s, out);
}

// round 11
// speedup vs baseline: 1.1970x; 1.1506x over previous
#include <cuda_runtime.h>
#include <cuda_fp16.h>
#include <cstdint>

#define TOK   4096
#define HID   2048
#define INTER 5632

// ---- scratch (device globals; no runtime allocation allowed) ----
__device__ __half g_xh[(size_t)TOK * HID];      // x in fp16
__device__ __half g_wg[(size_t)INTER * HID];    // gate_w fp16
__device__ __half g_wu[(size_t)INTER * HID];    // up_w fp16
__device__ __half g_wd[(size_t)HID * INTER];    // down_w fp16
__device__ __half g_hbuf[(size_t)TOK * INTER];  // hidden activation fp16

#define N4X ((TOK * HID) / 4)      // 2,097,152 float4
#define N4W ((INTER * HID) / 4)    // 2,883,584 float4
#define N4TOT (N4X + 3 * N4W)      // 10,747,904  (= 41984 * 256)

// ---- single fused fp32 -> fp16 conversion over all 4 tensors ----
__global__ __launch_bounds__(256)
void convert_all(const float* __restrict__ x,  const float* __restrict__ wg,
                 const float* __restrict__ wu, const float* __restrict__ wd,
                 __half* __restrict__ oxh, __half* __restrict__ owg,
                 __half* __restrict__ owu, __half* __restrict__ owd) {
  int i = blockIdx.x * blockDim.x + threadIdx.x;
  if (i >= N4TOT) return;
  const float* src;
  __half* dst;
  int off;
  if (i < N4X) { src = x; dst = oxh; off = i; }
  else {
    int j = i - N4X;
    int w = j / N4W;
    off = j - w * N4W;
    src = (w == 0) ? wg : (w == 1) ? wu : wd;
    dst = (w == 0) ? owg : (w == 1) ? owu : owd;
  }
  float4 v = reinterpret_cast<const float4*>(src)[off];
  __half2 h0 = __floats2half2_rn(v.x, v.y);
  __half2 h1 = __floats2half2_rn(v.z, v.w);
  reinterpret_cast<__half2*>(dst)[2 * off]     = h0;
  reinterpret_cast<__half2*>(dst)[2 * off + 1] = h1;
}

// =====================================================================
// helpers: mma.sync / ldmatrix / cp.async  (all valid on plain sm_103)
// =====================================================================
__device__ __forceinline__ uint32_t smem_u32(const void* p) {
  uint32_t a;
  asm("{ .reg .u64 t; cvta.to.shared.u64 t, %1; cvt.u32.u64 %0, t; }" : "=r"(a) : "l"(p));
  return a;
}

__device__ __forceinline__ void mma16816(float* c, const uint32_t* a, const uint32_t* b) {
  asm volatile(
      "mma.sync.aligned.m16n8k16.row.col.f32.f16.f16.f32 "
      "{%0,%1,%2,%3}, {%4,%5,%6,%7}, {%8,%9}, {%0,%1,%2,%3};\n"
      : "+f"(c[0]), "+f"(c[1]), "+f"(c[2]), "+f"(c[3])
      : "r"(a[0]), "r"(a[1]), "r"(a[2]), "r"(a[3]), "r"(b[0]), "r"(b[1]));
}

__device__ __forceinline__ void ldsm4(uint32_t* r, uint32_t addr) {
  asm volatile("ldmatrix.sync.aligned.m8n8.x4.shared.b16 {%0,%1,%2,%3}, [%4];"
               : "=r"(r[0]), "=r"(r[1]), "=r"(r[2]), "=r"(r[3]) : "r"(addr));
}

__device__ __forceinline__ void cp16(uint32_t s, const void* g) {
  asm volatile("cp.async.cg.shared.global [%0], [%1], 16;" :: "r"(s), "l"(g));
}
#define CP_COMMIT() asm volatile("cp.async.commit_group;" ::: "memory")

// BK = 64 halves = 128 bytes per row -> canonical SW128 swizzle.
// smem byte offset of (row, 16B-chunk c):  row*128 + ((c ^ (row&7)) << 4)

// =====================================================================
// GEMM1 fused gate+up: h = silu(X@Wg^T * gs) * (X@Wu^T * us), fp16 out
// CTA tile: M=128 x N=64 (per weight matrix), BK=64, 2-stage cp.async.
// 8 warps: wm=warp&3 (32 rows), wn=warp>>2 (32 cols); acc 32x32 per matrix.
// smem: stage s at s*32768: A(16KB) | Bg(8KB) | Bu(8KB)
// =====================================================================
__global__ __launch_bounds__(256, 2)
void gemm1_mma(const __half* __restrict__ X, const __half* __restrict__ Wg,
               const __half* __restrict__ Wu, const float* __restrict__ gs,
               const float* __restrict__ us, __half* __restrict__ Hout) {
  extern __shared__ char smem[];
  const uint32_t sb = smem_u32(smem);
  const int tid = threadIdx.x, lane = tid & 31, warp = tid >> 5;
  const int wm = warp & 3, wn = warp >> 2;       // wn in {0,1}
  const int mBase = blockIdx.y * 128;
  const int nBase = blockIdx.x * 64;
  const int s7 = lane & 7;

  const uint32_t aRow = (uint32_t)((wm * 32 + (lane & 15)) * 128);
  const int hiA = lane >> 4;
  const uint32_t bRow = (uint32_t)((wn * 32 + (lane & 7) + ((lane >> 4) & 1) * 8) * 128);
  const int cB = (lane >> 3) & 1;

  float ag[2][4][4], au[2][4][4];
#pragma unroll
  for (int i = 0; i < 2; i++)
#pragma unroll
    for (int j = 0; j < 4; j++)
#pragma unroll
      for (int k = 0; k < 4; k++) { ag[i][j][k] = 0.f; au[i][j][k] = 0.f; }

  auto load_stage = [&](int kt, int b) {
    const uint32_t base = sb + (uint32_t)b * 32768u;
    const int k0 = kt * 64;
#pragma unroll
    for (int i = 0; i < 4; i++) {               // A: 1024 chunks / 256 thr
      int ch = tid + i * 256;
      int row = ch >> 3, c = ch & 7;
      uint32_t sw = (uint32_t)(row * 128 + ((c ^ (row & 7)) << 4));
      cp16(base + sw, X + (size_t)(mBase + row) * HID + k0 + c * 8);
    }
#pragma unroll
    for (int i = 0; i < 2; i++) {               // Bg,Bu: 512 chunks each
      int ch = tid + i * 256;
      int row = ch >> 3, c = ch & 7;
      uint32_t sw = (uint32_t)(row * 128 + ((c ^ (row & 7)) << 4));
      cp16(base + 16384u + sw, Wg + (size_t)(nBase + row) * HID + k0 + c * 8);
      cp16(base + 24576u + sw, Wu + (size_t)(nBase + row) * HID + k0 + c * 8);
    }
    CP_COMMIT();
  };

  const int KT = HID / 64;  // 32
  load_stage(0, 0);
  load_stage(1, 1);

  for (int kt = 0; kt < KT; kt++) {
    const int b = kt & 1;
    if (kt + 1 < KT) asm volatile("cp.async.wait_group 1;" ::: "memory");
    else             asm volatile("cp.async.wait_group 0;" ::: "memory");
    __syncthreads();

    const uint32_t base = sb + (uint32_t)b * 32768u;
    const uint32_t aB = base + aRow;
    const uint32_t gB = base + 16384u + bRow;
    const uint32_t uB = base + 24576u + bRow;
#pragma unroll
    for (int kk = 0; kk < 4; kk++) {
      const uint32_t aOff = (uint32_t)((((kk * 2 + hiA) ^ s7)) << 4);
      uint32_t a[2][4];
      ldsm4(a[0], aB + aOff);
      ldsm4(a[1], aB + 2048u + aOff);
      const uint32_t bOff = (uint32_t)((((kk * 2 + cB) ^ s7)) << 4);
      uint32_t bg[2][4], bu[2][4];
#pragma unroll
      for (int np = 0; np < 2; np++) {
        ldsm4(bg[np], gB + (uint32_t)(np * 2048) + bOff);
        ldsm4(bu[np], uB + (uint32_t)(np * 2048) + bOff);
      }
#pragma unroll
      for (int mt = 0; mt < 2; mt++)
#pragma unroll
        for (int np = 0; np < 2; np++) {
          mma16816(ag[mt][np * 2 + 0], a[mt], &bg[np][0]);
          mma16816(ag[mt][np * 2 + 1], a[mt], &bg[np][2]);
          mma16816(au[mt][np * 2 + 0], a[mt], &bu[np][0]);
          mma16816(au[mt][np * 2 + 1], a[mt], &bu[np][2]);
        }
    }
    __syncthreads();
    if (kt + 2 < KT) load_stage(kt + 2, b);
  }

  // epilogue: dequant + silu-gate, fp16 out
  const int g = lane >> 2, t = lane & 3;
#pragma unroll
  for (int mt = 0; mt < 2; mt++) {
#pragma unroll
    for (int n8 = 0; n8 < 4; n8++) {
      const int col = nBase + wn * 32 + (n8 >> 1) * 16 + (n8 & 1) * 8 + 2 * t;
      const float gs0 = __ldg(gs + col), gs1 = __ldg(gs + col + 1);
      const float us0 = __ldg(us + col), us1 = __ldg(us + col + 1);
      const float* cg = ag[mt][n8];
      const float* cu = au[mt][n8];
      const int r = mBase + wm * 32 + mt * 16 + g;

      float g00 = cg[0] * gs0, g01 = cg[1] * gs1;
      float g10 = cg[2] * gs0, g11 = cg[3] * gs1;
      float u00 = cu[0] * us0, u01 = cu[1] * us1;
      float u10 = cu[2] * us0, u11 = cu[3] * us1;

      float h00 = g00 / (1.f + expf(-g00)) * u00;
      float h01 = g01 / (1.f + expf(-g01)) * u01;
      float h10 = g10 / (1.f + expf(-g10)) * u10;
      float h11 = g11 / (1.f + expf(-g11)) * u11;

      *reinterpret_cast<__half2*>(Hout + (size_t)r * INTER + col) =
          __floats2half2_rn(h00, h01);
      *reinterpret_cast<__half2*>(Hout + (size_t)(r + 8) * INTER + col) =
          __floats2half2_rn(h10, h11);
    }
  }
}

// =====================================================================
// GEMM2: out = (H @ Wd^T) * ds, fp32 out. CTA tile M=128 x N=128, BK=64.
// 8 warps: wm=warp&3 (32 rows), wn=warp>>2 (64 cols); warp 32x64.
// smem: stage s at s*32768: A(16KB) | B(16KB)
// =====================================================================
__global__ __launch_bounds__(256, 2)
void gemm2_mma(const __half* __restrict__ H, const __half* __restrict__ Wd,
               const float* __restrict__ ds, float* __restrict__ Out) {
  extern __shared__ char smem[];
  const uint32_t sb = smem_u32(smem);
  const int tid = threadIdx.x, lane = tid & 31, warp = tid >> 5;
  const int wm = warp & 3, wn = warp >> 2;       // wn in {0,1}
  const int mBase = blockIdx.y * 128;
  const int nBase = blockIdx.x * 128;
  const int s7 = lane & 7;

  const uint32_t aRow = (uint32_t)((wm * 32 + (lane & 15)) * 128);
  const int hiA = lane >> 4;
  const uint32_t bRow = (uint32_t)((wn * 64 + (lane & 7) + ((lane >> 4) & 1) * 8) * 128);
  const int cB = (lane >> 3) & 1;

  float acc[2][8][4];
#pragma unroll
  for (int i = 0; i < 2; i++)
#pragma unroll
    for (int j = 0; j < 8; j++)
#pragma unroll
      for (int k = 0; k < 4; k++) acc[i][j][k] = 0.f;

  auto load_stage = [&](int kt, int b) {
    const uint32_t base = sb + (uint32_t)b * 32768u;
    const int k0 = kt * 64;
#pragma unroll
    for (int i = 0; i < 4; i++) {
      int ch = tid + i * 256;
      int row = ch >> 3, c = ch & 7;
      uint32_t sw = (uint32_t)(row * 128 + ((c ^ (row & 7)) << 4));
      cp16(base + sw,          H  + (size_t)(mBase + row) * INTER + k0 + c * 8);
      cp16(base + 16384u + sw, Wd + (size_t)(nBase + row) * INTER + k0 + c * 8);
    }
    CP_COMMIT();
  };

  const int KT = INTER / 64;  // 88
  load_stage(0, 0);
  load_stage(1, 1);

  for (int kt = 0; kt < KT; kt++) {
    const int b = kt & 1;
    if (kt + 1 < KT) asm volatile("cp.async.wait_group 1;" ::: "memory");
    else             asm volatile("cp.async.wait_group 0;" ::: "memory");
    __syncthreads();

    const uint32_t base = sb + (uint32_t)b * 32768u;
    const uint32_t aB = base + aRow;
    const uint32_t bB = base + 16384u + bRow;
#pragma unroll
    for (int kk = 0; kk < 4; kk++) {
      const uint32_t aOff = (uint32_t)((((kk * 2 + hiA) ^ s7)) << 4);
      uint32_t a[2][4];
      ldsm4(a[0], aB + aOff);
      ldsm4(a[1], aB + 2048u + aOff);
      const uint32_t bOff = (uint32_t)((((kk * 2 + cB) ^ s7)) << 4);
      uint32_t bf[4][4];
#pragma unroll
      for (int np = 0; np < 4; np++)
        ldsm4(bf[np], bB + (uint32_t)(np * 2048) + bOff);
#pragma unroll
      for (int mt = 0; mt < 2; mt++)
#pragma unroll
        for (int np = 0; np < 4; np++) {
          mma16816(acc[mt][np * 2 + 0], a[mt], &bf[np][0]);
          mma16816(acc[mt][np * 2 + 1], a[mt], &bf[np][2]);
        }
    }
    __syncthreads();
    if (kt + 2 < KT) load_stage(kt + 2, b);
  }

  const int g = lane >> 2, t = lane & 3;
#pragma unroll
  for (int mt = 0; mt < 2; mt++) {
#pragma unroll
    for (int n8 = 0; n8 < 8; n8++) {
      const int col = nBase + wn * 64 + (n8 >> 1) * 16 + (n8 & 1) * 8 + 2 * t;
      const float d0 = __ldg(ds + col), d1 = __ldg(ds + col + 1);
      const float* cc = acc[mt][n8];
      const int r = mBase + wm * 32 + mt * 16 + g;
      *reinterpret_cast<float2*>(Out + (size_t)r * HID + col) =
          make_float2(cc[0] * d0, cc[1] * d1);
      *reinterpret_cast<float2*>(Out + (size_t)(r + 8) * HID + col) =
          make_float2(cc[2] * d0, cc[3] * d1);
    }
  }
}

// =====================================================================
extern "C" void kernel_launch(void* const* d_in, const int* in_sizes, int n_in,
                              void* d_out, int out_size) {
  const float* x      = (const float*)d_in[0];
  const float* gate_w = (const float*)d_in[1];
  const float* up_w   = (const float*)d_in[2];
  const float* down_w = (const float*)d_in[3];
  const float* gate_s = (const float*)d_in[4];
  const float* up_s   = (const float*)d_in[5];
  const float* down_s = (const float*)d_in[6];
  float* out = (float*)d_out;

  __half *xh, *wg, *wu, *wd, *hb;
  cudaGetSymbolAddress((void**)&xh, g_xh);
  cudaGetSymbolAddress((void**)&wg, g_wg);
  cudaGetSymbolAddress((void**)&wu, g_wu);
  cudaGetSymbolAddress((void**)&wd, g_wd);
  cudaGetSymbolAddress((void**)&hb, g_hbuf);

  const int SMEM = 65536;  // 2 stages x 32KB, both GEMMs
  cudaFuncSetAttribute(gemm1_mma, cudaFuncAttributeMaxDynamicSharedMemorySize, SMEM);
  cudaFuncSetAttribute(gemm2_mma, cudaFuncAttributeMaxDynamicSharedMemorySize, SMEM);

  // single fused convert: (N4TOT + 255)/256 = 41984 blocks
  convert_all<<<(N4TOT + 255) / 256, 256>>>(x, gate_w, up_w, down_w, xh, wg, wu, wd);

  dim3 grid1(INTER / 64, TOK / 128);   // (88, 32)
  gemm1_mma<<<grid1, 256, SMEM>>>(xh, wg, wu, gate_s, up_s, hb);

  dim3 grid2(HID / 128, TOK / 128);    // (16, 32)
  gemm2_mma<<<grid2, 256, SMEM>>>(hb, wd, down_s, out);
}